// round 16
// baseline (speedup 1.0000x reference)
#include <cuda_runtime.h>

#define NE 32
#define NUP 16
#define NA 8
#define DF 32
#define WH 16
#define KD 8
#define ED 16

typedef unsigned long long ull;

// ---- shared memory layout (float offsets, 16B-aligned) ----
#define OFF_W1   0        // [2][3][32][16] = 3072
#define OFF_B1   3072     // [2][3][16]     = 96
#define OFF_W2   3168     // [2][3][16][8]  = 768
#define OFF_B2   3936     // [2][3][8]      = 48
#define OFF_HW   3984     // [2][16][8]     = 256
#define OFF_HB   4240     // [2][8]         = 16
#define OFF_GW   4256     // [2][8][16]     = 256
#define OFF_GB   4512     // [2][16]        = 32
#define OFF_ORB  4544     // [16]
#define OFF_XE   4560     // [2][16]        = 32
#define OFF_Y    4592     // [8][8]         = 64
#define OFF_X    4656     // [32][16]       = 512
#define OFF_HX   5168     // [32][8]        = 256
#define OFF_Z0   5424     // [32][8]        = 256
#define OFF_Z1   5680     // [32][8]        = 256
#define OFF_WF1  5936     // [32][32][8]    = 8192
#define OFF_RED  14128
#define SMEM_FLOATS 14132

__device__ __forceinline__ void fma2(ull& d, ull a, ull b) {
    asm("fma.rn.f32x2 %0, %1, %2, %0;" : "+l"(d) : "l"(a), "l"(b));
}
__device__ __forceinline__ ull dup2(float x) {
    unsigned u = __float_as_uint(x);
    ull r; asm("mov.b64 %0, {%1, %2};" : "=l"(r) : "r"(u), "r"(u));
    return r;
}
__device__ __forceinline__ float2 unp2(ull p) {
    unsigned lo, hi;
    asm("mov.b64 {%0, %1}, %2;" : "=r"(lo), "=r"(hi) : "l"(p));
    return make_float2(__uint_as_float(lo), __uint_as_float(hi));
}
// ssp(x) = softplus(x) - ln2; inputs bounded, approx MUFU path
__device__ __forceinline__ float sspf(float x) {
    float t; asm("ex2.approx.ftz.f32 %0, %1;" : "=f"(t) : "f"(x * 1.4426950408889634f));
    float u; asm("lg2.approx.ftz.f32 %0, %1;" : "=f"(u) : "f"(1.0f + t));
    return fmaf(0.69314718055994531f, u, -0.69314718055994531f);
}

// ---- fused ssp + layer-2 (16 -> 8) + output ssp ----
__device__ __forceinline__ void finish_one(const ull* h1, const float* s, int sk, float* m)
{
    const float* w2  = s + OFF_W2 + (sk << 7);
    const ull*   b2p = (const ull*)(s + OFF_B2 + (sk << 3));
    ull o2[4];
    #pragma unroll
    for (int t = 0; t < 4; t++) o2[t] = b2p[t];
    #pragma unroll
    for (int t = 0; t < 8; t++) {
        float2 v = unp2(h1[t]);
        float a0 = sspf(v.x), a1 = sspf(v.y);
        const ulonglong2* wr0 = (const ulonglong2*)(w2 + ((2 * t) << 3));
        ulonglong2 x0 = wr0[0], x1 = wr0[1];
        ull pa = dup2(a0);
        fma2(o2[0], pa, x0.x); fma2(o2[1], pa, x0.y);
        fma2(o2[2], pa, x1.x); fma2(o2[3], pa, x1.y);
        const ulonglong2* wr1 = (const ulonglong2*)(w2 + ((2 * t + 1) << 3));
        ulonglong2 y0 = wr1[0], y1 = wr1[1];
        pa = dup2(a1);
        fma2(o2[0], pa, y0.x); fma2(o2[1], pa, y0.y);
        fma2(o2[2], pa, y1.x); fma2(o2[3], pa, y1.y);
    }
    #pragma unroll
    for (int t = 0; t < 4; t++) {
        float2 v = unp2(o2[t]);
        m[2*t] = sspf(v.x); m[2*t+1] = sspf(v.y);
    }
}

// one feature's dual-layer W1 accumulate: 8 LDS.128 + 1 dup + 16 fma2
#define H1F_1(ef, f) { \
    ull ep = dup2(ef); \
    const ulonglong2* wra = (const ulonglong2*)(w1a + ((f) << 4)); \
    const ulonglong2* wrb = (const ulonglong2*)(w1b + ((f) << 4)); \
    ulonglong2 a0 = wra[0], a1 = wra[1], a2 = wra[2], a3 = wra[3]; \
    fma2(hA[0], ep, a0.x); fma2(hA[1], ep, a0.y); \
    fma2(hA[2], ep, a1.x); fma2(hA[3], ep, a1.y); \
    fma2(hA[4], ep, a2.x); fma2(hA[5], ep, a2.y); \
    fma2(hA[6], ep, a3.x); fma2(hA[7], ep, a3.y); \
    ulonglong2 b0 = wrb[0], b1 = wrb[1], b2 = wrb[2], b3 = wrb[3]; \
    fma2(hB[0], ep, b0.x); fma2(hB[1], ep, b0.y); \
    fma2(hB[2], ep, b1.x); fma2(hB[3], ep, b1.y); \
    fma2(hB[4], ep, b2.x); fma2(hB[5], ep, b2.y); \
    fma2(hB[6], ep, b3.x); fma2(hB[7], ep, b3.y); }

#define H1F_4(e4v, fb) { \
    H1F_1((e4v).x, (fb));     H1F_1((e4v).y, (fb) + 1); \
    H1F_1((e4v).z, (fb) + 2); H1F_1((e4v).w, (fb) + 3); }

// fused dual-layer W1 pass over all 32 features (features dead afterwards)
#define H1_EDGE(skA_, skB_) { \
    const float* w1a = s + OFF_W1 + ((skA_) << 9); \
    const float* w1b = s + OFF_W1 + ((skB_) << 9); \
    const ull* b1a = (const ull*)(s + OFF_B1 + ((skA_) << 4)); \
    const ull* b1b = (const ull*)(s + OFF_B1 + ((skB_) << 4)); \
    _Pragma("unroll") \
    for (int t = 0; t < 8; t++) { hA[t] = b1a[t]; hB[t] = b1b[t]; } \
    H1F_4(ev0, 0);  H1F_4(ev1, 4);  H1F_4(ev2, 8);  H1F_4(ev3, 12); \
    H1F_4(ev4, 16); H1F_4(ev5, 20); H1F_4(ev6, 24); H1F_4(ev7, 28); }

#define LOADEV(ptr) { \
    const float4* _p = (const float4*)(ptr); \
    ev0 = _p[0]; ev1 = _p[1]; ev2 = _p[2]; ev3 = _p[3]; \
    ev4 = _p[4]; ev5 = _p[5]; ev6 = _p[6]; ev7 = _p[7]; }

// layer-0 elec epilogue: *hx*mask, 16-lane xor-reduce, atomic scatter
#define EPI_L0(hxadd, zadd, mk) { \
    const float4* hx = (const float4*)(s + (hxadd)); \
    float4 h0 = hx[0], h1v = hx[1]; \
    m[0] *= h0.x * (mk);  m[1] *= h0.y * (mk); \
    m[2] *= h0.z * (mk);  m[3] *= h0.w * (mk); \
    m[4] *= h1v.x * (mk); m[5] *= h1v.y * (mk); \
    m[6] *= h1v.z * (mk); m[7] *= h1v.w * (mk); \
    _Pragma("unroll") \
    for (int k = 0; k < 8; k++) { \
        m[k] += __shfl_xor_sync(0xffffffffu, m[k], 1); \
        m[k] += __shfl_xor_sync(0xffffffffu, m[k], 2); \
        m[k] += __shfl_xor_sync(0xffffffffu, m[k], 4); \
        m[k] += __shfl_xor_sync(0xffffffffu, m[k], 8); } \
    if ((lane & 15) == 0) { \
        _Pragma("unroll") \
        for (int k = 0; k < 8; k++) atomicAdd(&s[(zadd) + k], m[k]); } }

#define ST_WF1(wfadd, mk) { \
    float4* d4 = (float4*)(s + (wfadd)); \
    d4[0] = make_float4(m[0]*(mk), m[1]*(mk), m[2]*(mk), m[3]*(mk)); \
    d4[1] = make_float4(m[4]*(mk), m[5]*(mk), m[6]*(mk), m[7]*(mk)); }

__global__ void __launch_bounds__(256, 3)
jastrow_kernel(const float* __restrict__ ee,   // [B,32,32,32]
               const float* __restrict__ en,   // [B,32,8,32]
               const float* __restrict__ Xemb,
               const float* __restrict__ Yv,
               const float* __restrict__ wW1,
               const float* __restrict__ wb1,
               const float* __restrict__ wW2,
               const float* __restrict__ wb2,
               const float* __restrict__ hW,
               const float* __restrict__ hb,
               const float* __restrict__ gW,
               const float* __restrict__ gb,
               const float* __restrict__ orbW,
               float* __restrict__ out)
{
    extern __shared__ float s[];
    const int tid  = threadIdx.x;
    const int lane = tid & 31;
    const int b    = blockIdx.x;

    float4 ev0, ev1, ev2, ev3, ev4, ev5, ev6, ev7;
    // edge 0 base: (i0*32 + j0)*32 floats into sample b
    const float* ebase = ee + ((size_t)b << 15) + ((tid >> 4) << 10) + ((tid & 15) << 5);
    // hoisted load of edge 0: hidden under the SMEM-init phase
    LOADEV(ebase);

    for (int t = tid; t < 3072; t += 256) s[OFF_W1 + t] = wW1[t];
    for (int t = tid; t < 96;   t += 256) s[OFF_B1 + t] = wb1[t];
    for (int t = tid; t < 768;  t += 256) s[OFF_W2 + t] = wW2[t];
    for (int t = tid; t < 48;   t += 256) s[OFF_B2 + t] = wb2[t];
    for (int t = tid; t < 256;  t += 256) s[OFF_HW + t] = hW[t];
    for (int t = tid; t < 16;   t += 256) s[OFF_HB + t] = hb[t];
    for (int t = tid; t < 256;  t += 256) s[OFF_GW + t] = gW[t];
    for (int t = tid; t < 32;   t += 256) s[OFF_GB + t] = gb[t];
    for (int t = tid; t < 16;   t += 256) s[OFF_ORB + t] = orbW[t];
    for (int t = tid; t < 32;   t += 256) s[OFF_XE + t] = Xemb[t];
    for (int t = tid; t < 64;   t += 256) s[OFF_Y + t]  = Yv[t];
    s[OFF_Z0 + tid] = 0.f;
    s[OFF_Z1 + tid] = 0.f;
    if (tid == 0) s[OFF_RED] = 0.f;
    for (int t = tid; t < NE * ED; t += 256) {
        int i = t >> 4;
        s[OFF_X + t] = Xemb[((i >= NUP) ? ED : 0) + (t & 15)];
    }
    __syncthreads();

    // hx0[j][k] = ssp(x0[j] @ hW0 + hb0)
    {
        int j = tid >> 3, k = tid & 7;
        float a = s[OFF_HB + k];
        #pragma unroll
        for (int ei = 0; ei < ED; ei++)
            a = fmaf(s[OFF_X + j * ED + ei], s[OFF_HW + ei * KD + k], a);
        s[OFF_HX + tid] = sspf(a);
    }
    __syncthreads();

    // ============ edge phase: straight-line, fused dual-layer W1 ============
    const float md = ((tid >> 4) == (tid & 15)) ? 0.f : 1.f;
    const int hxA = OFF_HX + ((tid & 15) << 3);           // hx[j0]
    const int z0A = OFF_Z0 + ((tid >> 4) << 3);           // Z0[i0]
    const int wfA = OFF_WF1 + ((tid >> 4) << 8) + ((tid & 15) << 3); // WF1[i0][j0]

    ull   hA[8], hB[8];
    float m[8];

    // ---- E0: (i0, j0), c=0
    H1_EDGE(0, 3);
    LOADEV(ebase + 16896);                 // prefetch E1 = (i0+16, j0+16)
    finish_one(hA, s, 0, m);
    EPI_L0(hxA, z0A, md);
    finish_one(hB, s, 3, m);
    ST_WF1(wfA, md);

    // ---- E1: (i0+16, j0+16), c=0
    H1_EDGE(0, 3);
    LOADEV(ebase + 512);                   // prefetch E2 = (i0, j0+16)
    finish_one(hA, s, 0, m);
    EPI_L0(hxA + 128, z0A + 128, md);
    finish_one(hB, s, 3, m);
    ST_WF1(wfA + 4224, md);

    // ---- E2: (i0, j0+16), c=1
    H1_EDGE(1, 4);
    LOADEV(ebase + 16384);                 // prefetch E3 = (i0+16, j0)
    finish_one(hA, s, 1, m);
    EPI_L0(hxA + 128, z0A, 1.f);
    finish_one(hB, s, 4, m);
    ST_WF1(wfA + 128, 1.f);

    // ---- E3: (i0+16, j0), c=1
    H1_EDGE(1, 4);
    // prefetch nuclear edge (iN = tid>>3, jN = tid&7)
    LOADEV(en + ((size_t)b << 13) + ((tid >> 3) << 8) + ((tid & 7) << 5));
    finish_one(hA, s, 1, m);
    EPI_L0(hxA, z0A + 128, 1.f);
    finish_one(hB, s, 4, m);
    ST_WF1(wfA + 4096, 1.f);

    // ---- NUC: (iN, jN), c=2, both layers contract with Y
    H1_EDGE(2, 5);
    {
        const float4* yr = (const float4*)(s + OFF_Y + ((tid & 7) << 3));
        float4 y0 = yr[0], y1 = yr[1];
        const int zN = (tid >> 3) << 3;

        finish_one(hA, s, 2, m);
        m[0] *= y0.x; m[1] *= y0.y; m[2] *= y0.z; m[3] *= y0.w;
        m[4] *= y1.x; m[5] *= y1.y; m[6] *= y1.z; m[7] *= y1.w;
        #pragma unroll
        for (int k = 0; k < 8; k++) {
            m[k] += __shfl_xor_sync(0xffffffffu, m[k], 1);
            m[k] += __shfl_xor_sync(0xffffffffu, m[k], 2);
            m[k] += __shfl_xor_sync(0xffffffffu, m[k], 4);
        }
        if ((lane & 7) == 0) {
            #pragma unroll
            for (int k = 0; k < 8; k++)
                atomicAdd(&s[OFF_Z0 + zN + k], m[k]);
        }

        finish_one(hB, s, 5, m);
        m[0] *= y0.x; m[1] *= y0.y; m[2] *= y0.z; m[3] *= y0.w;
        m[4] *= y1.x; m[5] *= y1.y; m[6] *= y1.z; m[7] *= y1.w;
        #pragma unroll
        for (int k = 0; k < 8; k++) {
            m[k] += __shfl_xor_sync(0xffffffffu, m[k], 1);
            m[k] += __shfl_xor_sync(0xffffffffu, m[k], 2);
            m[k] += __shfl_xor_sync(0xffffffffu, m[k], 4);
        }
        if ((lane & 7) == 0) {
            #pragma unroll
            for (int k = 0; k < 8; k++)
                atomicAdd(&s[OFF_Z1 + zN + k], m[k]);
        }
    }
    __syncthreads();

    // ============ layer-0 update: x += Z0 @ gW0 + gb0 ============
    for (int t = tid; t < NE * ED; t += 256) {
        int i = t >> 4, ei = t & 15;
        float a = s[OFF_GB + ei];
        #pragma unroll
        for (int k = 0; k < KD; k++)
            a = fmaf(s[OFF_Z0 + i * KD + k], s[OFF_GW + k * ED + ei], a);
        s[OFF_X + t] += a;
    }
    __syncthreads();

    // hx1[j][k] = ssp(x1[j] @ hW1 + hb1)
    {
        int j = tid >> 3, k = tid & 7;
        float a = s[OFF_HB + KD + k];
        #pragma unroll
        for (int ei = 0; ei < ED; ei++)
            a = fmaf(s[OFF_X + j * ED + ei], s[OFF_HW + (ED + ei) * KD + k], a);
        s[OFF_HX + tid] = sspf(a);
    }
    __syncthreads();

    // z1[i][k] += sum_j WF1[i][j][k] * hx1[j][k]
    {
        int i = tid >> 3, k = tid & 7;
        float a = s[OFF_Z1 + tid];
        const float* wf = s + OFF_WF1 + (i << 8) + k;
        #pragma unroll
        for (int j = 0; j < NE; j++)
            a = fmaf(wf[j << 3], s[OFF_HX + (j << 3) + k], a);
        s[OFF_Z1 + tid] = a;
    }
    __syncthreads();

    // layer-1 update: x += Z1 @ gW1 + gb1
    for (int t = tid; t < NE * ED; t += 256) {
        int i = t >> 4, ei = t & 15;
        float a = s[OFF_GB + ED + ei];
        #pragma unroll
        for (int k = 0; k < KD; k++)
            a = fmaf(s[OFF_Z1 + i * KD + k], s[OFF_GW + (KD + k) * ED + ei], a);
        s[OFF_X + t] += a;
    }
    __syncthreads();

    // readout
    float part = 0.f;
    for (int t = tid; t < NE * ED; t += 256)
        part += s[OFF_X + t] * s[OFF_ORB + (t & 15)];
    #pragma unroll
    for (int off = 16; off > 0; off >>= 1)
        part += __shfl_down_sync(0xffffffffu, part, off);
    if (lane == 0) atomicAdd(&s[OFF_RED], part);
    __syncthreads();
    if (tid == 0) out[b] = s[OFF_RED];
}

extern "C" void kernel_launch(void* const* d_in, const int* in_sizes, int n_in,
                              void* d_out, int out_size) {
    const float* ee   = (const float*)d_in[0];
    const float* en   = (const float*)d_in[1];
    const float* Xemb = (const float*)d_in[2];
    const float* Yv   = (const float*)d_in[3];
    const float* wW1  = (const float*)d_in[4];
    const float* wb1  = (const float*)d_in[5];
    const float* wW2  = (const float*)d_in[6];
    const float* wb2  = (const float*)d_in[7];
    const float* hW   = (const float*)d_in[8];
    const float* hb   = (const float*)d_in[9];
    const float* gW   = (const float*)d_in[10];
    const float* gb   = (const float*)d_in[11];
    const float* orbW = (const float*)d_in[12];
    float* out = (float*)d_out;

    size_t smem = SMEM_FLOATS * sizeof(float);
    cudaFuncSetAttribute(jastrow_kernel,
                         cudaFuncAttributeMaxDynamicSharedMemorySize, (int)smem);
    jastrow_kernel<<<512, 256, smem>>>(ee, en, Xemb, Yv, wW1, wb1, wW2, wb2,
                                       hW, hb, gW, gb, orbW, out);
}

// round 17
// speedup vs baseline: 1.3972x; 1.3972x over previous
#include <cuda_runtime.h>

#define NE 32
#define NUP 16
#define NA 8
#define DF 32
#define WH 16
#define KD 8
#define ED 16

typedef unsigned long long ull;

// ---- shared memory layout (float offsets, 16B-aligned) ----
#define OFF_W1   0        // [2][3][32][16] = 3072
#define OFF_B1   3072     // [2][3][16]     = 96
#define OFF_W2   3168     // [2][3][16][8]  = 768
#define OFF_B2   3936     // [2][3][8]      = 48
#define OFF_HW   3984     // [2][16][8]     = 256
#define OFF_HB   4240     // [2][8]         = 16
#define OFF_GW   4256     // [2][8][16]     = 256
#define OFF_GB   4512     // [2][16]        = 32
#define OFF_ORB  4544     // [16]
#define OFF_XE   4560     // [2][16]        = 32
#define OFF_Y    4592     // [8][8]         = 64
#define OFF_X    4656     // [32][16]       = 512
#define OFF_HX   5168     // [32][8]        = 256
#define OFF_Z0   5424     // [32][8]        = 256
#define OFF_Z1   5680     // [32][8]        = 256
#define OFF_WF1  5936     // [32][32][8]    = 8192
#define OFF_RED  14128
#define SMEM_FLOATS 14132

__device__ __forceinline__ void fma2(ull& d, ull a, ull b) {
    asm("fma.rn.f32x2 %0, %1, %2, %0;" : "+l"(d) : "l"(a), "l"(b));
}
__device__ __forceinline__ ull dup2(float x) {
    unsigned u = __float_as_uint(x);
    ull r; asm("mov.b64 %0, {%1, %2};" : "=l"(r) : "r"(u), "r"(u));
    return r;
}
__device__ __forceinline__ float2 unp2(ull p) {
    unsigned lo, hi;
    asm("mov.b64 {%0, %1}, %2;" : "=r"(lo), "=r"(hi) : "l"(p));
    return make_float2(__uint_as_float(lo), __uint_as_float(hi));
}
// ssp(x) = softplus(x) - ln2; inputs bounded, approx MUFU path
__device__ __forceinline__ float sspf(float x) {
    float t; asm("ex2.approx.ftz.f32 %0, %1;" : "=f"(t) : "f"(x * 1.4426950408889634f));
    float u; asm("lg2.approx.ftz.f32 %0, %1;" : "=f"(u) : "f"(1.0f + t));
    return fmaf(0.69314718055994531f, u, -0.69314718055994531f);
}

// ---- fused ssp + layer-2 (16 -> 8) + output ssp ----
__device__ __forceinline__ void finish_one(const ull* h1, const float* s, int sk, float* m)
{
    const float* w2  = s + OFF_W2 + (sk << 7);
    const ull*   b2p = (const ull*)(s + OFF_B2 + (sk << 3));
    ull o2[4];
    #pragma unroll
    for (int t = 0; t < 4; t++) o2[t] = b2p[t];
    #pragma unroll
    for (int t = 0; t < 8; t++) {
        float2 v = unp2(h1[t]);
        float a0 = sspf(v.x), a1 = sspf(v.y);
        const ulonglong2* wr0 = (const ulonglong2*)(w2 + ((2 * t) << 3));
        ulonglong2 x0 = wr0[0], x1 = wr0[1];
        ull pa = dup2(a0);
        fma2(o2[0], pa, x0.x); fma2(o2[1], pa, x0.y);
        fma2(o2[2], pa, x1.x); fma2(o2[3], pa, x1.y);
        const ulonglong2* wr1 = (const ulonglong2*)(w2 + ((2 * t + 1) << 3));
        ulonglong2 y0 = wr1[0], y1 = wr1[1];
        pa = dup2(a1);
        fma2(o2[0], pa, y0.x); fma2(o2[1], pa, y0.y);
        fma2(o2[2], pa, y1.x); fma2(o2[3], pa, y1.y);
    }
    #pragma unroll
    for (int t = 0; t < 4; t++) {
        float2 v = unp2(o2[t]);
        m[2*t] = sspf(v.x); m[2*t+1] = sspf(v.y);
    }
}

// one feature's dual-layer W1 accumulate: 8 LDS.128 + 1 dup + 16 fma2
#define H1F_1(ef, f) { \
    ull ep = dup2(ef); \
    const ulonglong2* wra = (const ulonglong2*)(w1a + ((f) << 4)); \
    const ulonglong2* wrb = (const ulonglong2*)(w1b + ((f) << 4)); \
    ulonglong2 a0 = wra[0], a1 = wra[1], a2 = wra[2], a3 = wra[3]; \
    fma2(hA[0], ep, a0.x); fma2(hA[1], ep, a0.y); \
    fma2(hA[2], ep, a1.x); fma2(hA[3], ep, a1.y); \
    fma2(hA[4], ep, a2.x); fma2(hA[5], ep, a2.y); \
    fma2(hA[6], ep, a3.x); fma2(hA[7], ep, a3.y); \
    ulonglong2 b0 = wrb[0], b1 = wrb[1], b2 = wrb[2], b3 = wrb[3]; \
    fma2(hB[0], ep, b0.x); fma2(hB[1], ep, b0.y); \
    fma2(hB[2], ep, b1.x); fma2(hB[3], ep, b1.y); \
    fma2(hB[4], ep, b2.x); fma2(hB[5], ep, b2.y); \
    fma2(hB[6], ep, b3.x); fma2(hB[7], ep, b3.y); }

#define H1F_4(e4v, fb) { \
    H1F_1((e4v).x, (fb));     H1F_1((e4v).y, (fb) + 1); \
    H1F_1((e4v).z, (fb) + 2); H1F_1((e4v).w, (fb) + 3); }

// fused dual-layer W1 pass over all 32 features (features dead afterwards)
#define H1_EDGE(skA_, skB_) { \
    const float* w1a = s + OFF_W1 + ((skA_) << 9); \
    const float* w1b = s + OFF_W1 + ((skB_) << 9); \
    const ull* b1a = (const ull*)(s + OFF_B1 + ((skA_) << 4)); \
    const ull* b1b = (const ull*)(s + OFF_B1 + ((skB_) << 4)); \
    _Pragma("unroll") \
    for (int t = 0; t < 8; t++) { hA[t] = b1a[t]; hB[t] = b1b[t]; } \
    H1F_4(ev0, 0);  H1F_4(ev1, 4);  H1F_4(ev2, 8);  H1F_4(ev3, 12); \
    H1F_4(ev4, 16); H1F_4(ev5, 20); H1F_4(ev6, 24); H1F_4(ev7, 28); }

#define LOADEV(ptr) { \
    const float4* _p = (const float4*)(ptr); \
    ev0 = _p[0]; ev1 = _p[1]; ev2 = _p[2]; ev3 = _p[3]; \
    ev4 = _p[4]; ev5 = _p[5]; ev6 = _p[6]; ev7 = _p[7]; }

// layer-0 elec epilogue: *hx*mask, 16-lane xor-reduce, atomic scatter
#define EPI_L0(hxadd, zadd, mk) { \
    const float4* hx = (const float4*)(s + (hxadd)); \
    float4 h0 = hx[0], h1v = hx[1]; \
    m[0] *= h0.x * (mk);  m[1] *= h0.y * (mk); \
    m[2] *= h0.z * (mk);  m[3] *= h0.w * (mk); \
    m[4] *= h1v.x * (mk); m[5] *= h1v.y * (mk); \
    m[6] *= h1v.z * (mk); m[7] *= h1v.w * (mk); \
    _Pragma("unroll") \
    for (int k = 0; k < 8; k++) { \
        m[k] += __shfl_xor_sync(0xffffffffu, m[k], 1); \
        m[k] += __shfl_xor_sync(0xffffffffu, m[k], 2); \
        m[k] += __shfl_xor_sync(0xffffffffu, m[k], 4); \
        m[k] += __shfl_xor_sync(0xffffffffu, m[k], 8); } \
    if ((lane & 15) == 0) { \
        _Pragma("unroll") \
        for (int k = 0; k < 8; k++) atomicAdd(&s[(zadd) + k], m[k]); } }

#define ST_WF1(wfadd, mk) { \
    float4* d4 = (float4*)(s + (wfadd)); \
    d4[0] = make_float4(m[0]*(mk), m[1]*(mk), m[2]*(mk), m[3]*(mk)); \
    d4[1] = make_float4(m[4]*(mk), m[5]*(mk), m[6]*(mk), m[7]*(mk)); }

__global__ void __launch_bounds__(256, 2)
jastrow_kernel(const float* __restrict__ ee,   // [B,32,32,32]
               const float* __restrict__ en,   // [B,32,8,32]
               const float* __restrict__ Xemb,
               const float* __restrict__ Yv,
               const float* __restrict__ wW1,
               const float* __restrict__ wb1,
               const float* __restrict__ wW2,
               const float* __restrict__ wb2,
               const float* __restrict__ hW,
               const float* __restrict__ hb,
               const float* __restrict__ gW,
               const float* __restrict__ gb,
               const float* __restrict__ orbW,
               float* __restrict__ out)
{
    extern __shared__ float s[];
    const int tid  = threadIdx.x;
    const int lane = tid & 31;
    const int b    = blockIdx.x;

    float4 ev0, ev1, ev2, ev3, ev4, ev5, ev6, ev7;
    // edge 0 base: (i0*32 + j0)*32 floats into sample b
    const float* ebase = ee + ((size_t)b << 15) + ((tid >> 4) << 10) + ((tid & 15) << 5);
    // hoisted load of edge 0: hidden under the SMEM-init phase
    LOADEV(ebase);

    for (int t = tid; t < 3072; t += 256) s[OFF_W1 + t] = wW1[t];
    for (int t = tid; t < 96;   t += 256) s[OFF_B1 + t] = wb1[t];
    for (int t = tid; t < 768;  t += 256) s[OFF_W2 + t] = wW2[t];
    for (int t = tid; t < 48;   t += 256) s[OFF_B2 + t] = wb2[t];
    for (int t = tid; t < 256;  t += 256) s[OFF_HW + t] = hW[t];
    for (int t = tid; t < 16;   t += 256) s[OFF_HB + t] = hb[t];
    for (int t = tid; t < 256;  t += 256) s[OFF_GW + t] = gW[t];
    for (int t = tid; t < 32;   t += 256) s[OFF_GB + t] = gb[t];
    for (int t = tid; t < 16;   t += 256) s[OFF_ORB + t] = orbW[t];
    for (int t = tid; t < 32;   t += 256) s[OFF_XE + t] = Xemb[t];
    for (int t = tid; t < 64;   t += 256) s[OFF_Y + t]  = Yv[t];
    s[OFF_Z0 + tid] = 0.f;
    s[OFF_Z1 + tid] = 0.f;
    if (tid == 0) s[OFF_RED] = 0.f;
    for (int t = tid; t < NE * ED; t += 256) {
        int i = t >> 4;
        s[OFF_X + t] = Xemb[((i >= NUP) ? ED : 0) + (t & 15)];
    }
    __syncthreads();

    // hx0[j][k] = ssp(x0[j] @ hW0 + hb0)
    {
        int j = tid >> 3, k = tid & 7;
        float a = s[OFF_HB + k];
        #pragma unroll
        for (int ei = 0; ei < ED; ei++)
            a = fmaf(s[OFF_X + j * ED + ei], s[OFF_HW + ei * KD + k], a);
        s[OFF_HX + tid] = sspf(a);
    }
    __syncthreads();

    // ============ edge phase: straight-line, fused dual-layer W1 ============
    const float md = ((tid >> 4) == (tid & 15)) ? 0.f : 1.f;
    const int hxA = OFF_HX + ((tid & 15) << 3);           // hx[j0]
    const int z0A = OFF_Z0 + ((tid >> 4) << 3);           // Z0[i0]
    const int wfA = OFF_WF1 + ((tid >> 4) << 8) + ((tid & 15) << 3); // WF1[i0][j0]

    ull   hA[8], hB[8];
    float m[8];

    // ---- E0: (i0, j0), c=0
    H1_EDGE(0, 3);
    LOADEV(ebase + 16896);                 // prefetch E1 = (i0+16, j0+16)
    finish_one(hA, s, 0, m);
    EPI_L0(hxA, z0A, md);
    finish_one(hB, s, 3, m);
    ST_WF1(wfA, md);

    // ---- E1: (i0+16, j0+16), c=0
    H1_EDGE(0, 3);
    LOADEV(ebase + 512);                   // prefetch E2 = (i0, j0+16)
    finish_one(hA, s, 0, m);
    EPI_L0(hxA + 128, z0A + 128, md);
    finish_one(hB, s, 3, m);
    ST_WF1(wfA + 4224, md);

    // ---- E2: (i0, j0+16), c=1
    H1_EDGE(1, 4);
    LOADEV(ebase + 16384);                 // prefetch E3 = (i0+16, j0)
    finish_one(hA, s, 1, m);
    EPI_L0(hxA + 128, z0A, 1.f);
    finish_one(hB, s, 4, m);
    ST_WF1(wfA + 128, 1.f);

    // ---- E3: (i0+16, j0), c=1
    H1_EDGE(1, 4);
    // prefetch nuclear edge (iN = tid>>3, jN = tid&7)
    LOADEV(en + ((size_t)b << 13) + ((tid >> 3) << 8) + ((tid & 7) << 5));
    finish_one(hA, s, 1, m);
    EPI_L0(hxA, z0A + 128, 1.f);
    finish_one(hB, s, 4, m);
    ST_WF1(wfA + 4096, 1.f);

    // ---- NUC: (iN, jN), c=2, both layers contract with Y
    H1_EDGE(2, 5);
    {
        const float4* yr = (const float4*)(s + OFF_Y + ((tid & 7) << 3));
        float4 y0 = yr[0], y1 = yr[1];
        const int zN = (tid >> 3) << 3;

        finish_one(hA, s, 2, m);
        m[0] *= y0.x; m[1] *= y0.y; m[2] *= y0.z; m[3] *= y0.w;
        m[4] *= y1.x; m[5] *= y1.y; m[6] *= y1.z; m[7] *= y1.w;
        #pragma unroll
        for (int k = 0; k < 8; k++) {
            m[k] += __shfl_xor_sync(0xffffffffu, m[k], 1);
            m[k] += __shfl_xor_sync(0xffffffffu, m[k], 2);
            m[k] += __shfl_xor_sync(0xffffffffu, m[k], 4);
        }
        if ((lane & 7) == 0) {
            #pragma unroll
            for (int k = 0; k < 8; k++)
                atomicAdd(&s[OFF_Z0 + zN + k], m[k]);
        }

        finish_one(hB, s, 5, m);
        m[0] *= y0.x; m[1] *= y0.y; m[2] *= y0.z; m[3] *= y0.w;
        m[4] *= y1.x; m[5] *= y1.y; m[6] *= y1.z; m[7] *= y1.w;
        #pragma unroll
        for (int k = 0; k < 8; k++) {
            m[k] += __shfl_xor_sync(0xffffffffu, m[k], 1);
            m[k] += __shfl_xor_sync(0xffffffffu, m[k], 2);
            m[k] += __shfl_xor_sync(0xffffffffu, m[k], 4);
        }
        if ((lane & 7) == 0) {
            #pragma unroll
            for (int k = 0; k < 8; k++)
                atomicAdd(&s[OFF_Z1 + zN + k], m[k]);
        }
    }
    __syncthreads();

    // ============ layer-0 update: x += Z0 @ gW0 + gb0 ============
    for (int t = tid; t < NE * ED; t += 256) {
        int i = t >> 4, ei = t & 15;
        float a = s[OFF_GB + ei];
        #pragma unroll
        for (int k = 0; k < KD; k++)
            a = fmaf(s[OFF_Z0 + i * KD + k], s[OFF_GW + k * ED + ei], a);
        s[OFF_X + t] += a;
    }
    __syncthreads();

    // hx1[j][k] = ssp(x1[j] @ hW1 + hb1)
    {
        int j = tid >> 3, k = tid & 7;
        float a = s[OFF_HB + KD + k];
        #pragma unroll
        for (int ei = 0; ei < ED; ei++)
            a = fmaf(s[OFF_X + j * ED + ei], s[OFF_HW + (ED + ei) * KD + k], a);
        s[OFF_HX + tid] = sspf(a);
    }
    __syncthreads();

    // z1[i][k] += sum_j WF1[i][j][k] * hx1[j][k]
    {
        int i = tid >> 3, k = tid & 7;
        float a = s[OFF_Z1 + tid];
        const float* wf = s + OFF_WF1 + (i << 8) + k;
        #pragma unroll
        for (int j = 0; j < NE; j++)
            a = fmaf(wf[j << 3], s[OFF_HX + (j << 3) + k], a);
        s[OFF_Z1 + tid] = a;
    }
    __syncthreads();

    // layer-1 update: x += Z1 @ gW1 + gb1
    for (int t = tid; t < NE * ED; t += 256) {
        int i = t >> 4, ei = t & 15;
        float a = s[OFF_GB + ED + ei];
        #pragma unroll
        for (int k = 0; k < KD; k++)
            a = fmaf(s[OFF_Z1 + i * KD + k], s[OFF_GW + (KD + k) * ED + ei], a);
        s[OFF_X + t] += a;
    }
    __syncthreads();

    // readout
    float part = 0.f;
    for (int t = tid; t < NE * ED; t += 256)
        part += s[OFF_X + t] * s[OFF_ORB + (t & 15)];
    #pragma unroll
    for (int off = 16; off > 0; off >>= 1)
        part += __shfl_down_sync(0xffffffffu, part, off);
    if (lane == 0) atomicAdd(&s[OFF_RED], part);
    __syncthreads();
    if (tid == 0) out[b] = s[OFF_RED];
}

extern "C" void kernel_launch(void* const* d_in, const int* in_sizes, int n_in,
                              void* d_out, int out_size) {
    const float* ee   = (const float*)d_in[0];
    const float* en   = (const float*)d_in[1];
    const float* Xemb = (const float*)d_in[2];
    const float* Yv   = (const float*)d_in[3];
    const float* wW1  = (const float*)d_in[4];
    const float* wb1  = (const float*)d_in[5];
    const float* wW2  = (const float*)d_in[6];
    const float* wb2  = (const float*)d_in[7];
    const float* hW   = (const float*)d_in[8];
    const float* hb   = (const float*)d_in[9];
    const float* gW   = (const float*)d_in[10];
    const float* gb   = (const float*)d_in[11];
    const float* orbW = (const float*)d_in[12];
    float* out = (float*)d_out;

    size_t smem = SMEM_FLOATS * sizeof(float);
    cudaFuncSetAttribute(jastrow_kernel,
                         cudaFuncAttributeMaxDynamicSharedMemorySize, (int)smem);
    jastrow_kernel<<<512, 256, smem>>>(ee, en, Xemb, Yv, wW1, wb1, wW2, wb2,
                                       hW, hb, gW, gb, orbW, out);
}